// round 1
// baseline (speedup 1.0000x reference)
#include <cuda_runtime.h>

// Problem constants (fixed by setup_inputs)
#define S_DIM 1024
#define I_DIM 2048
#define O_DIMX 1024
#define TOTAL 4096
#define BATCH 2048
#define IN_DIM 1024
#define NC 1000

// Scratch (no cudaMalloc allowed)
__device__ float g_E[BATCH * S_DIM];      // 8 MB
__device__ float g_Za[BATCH * TOTAL];     // 32 MB
__device__ float g_Zb[BATCH * TOTAL];     // 32 MB

#define BM 128
#define BN 128
#define BK 16
#define TM 8
#define TN 8

// C[M,N] = op( A[M,K] @ B + inj + bias )
// BT=false: B stored [K,N] row-major (ldb = row stride)   -- used for W
// BT=true : B stored [N,K] row-major (ldb = row stride)   -- used for Wp, Wo (B^T GEMM)
// INJ: add inj[row*S_DIM + col] for col < S_DIM
// BIAS: add bias[col]
// RELU: clamp at 0
template<bool BT, bool RELU, bool INJ, bool BIAS>
__global__ __launch_bounds__(256, 2)
void gemm_k(const float* __restrict__ A, int lda,
            const float* __restrict__ B, int ldb,
            float* __restrict__ C, int ldc,
            int N, int K,
            const float* __restrict__ inj,
            const float* __restrict__ bias)
{
    __shared__ float As[2][BK][BM];
    __shared__ float Bs[2][BK][BN];

    const int tid = threadIdx.x;
    const int tx  = tid & 15;       // 0..15  (N direction)
    const int ty  = tid >> 4;       // 0..15  (M direction)
    const int bm  = blockIdx.y * BM;
    const int bn  = blockIdx.x * BN;

    // A-load mapping: 128 rows x 4 float4; each thread does rows (ar, ar+64), float4 #ac4
    const int ar  = tid >> 2;       // 0..63
    const int ac4 = tid & 3;        // 0..3
    // B-load mapping (KN): 16 rows x 32 float4; each thread rows (bkr, bkr+8), float4 #bc4
    const int bkr = tid >> 5;       // 0..7
    const int bc4 = tid & 31;       // 0..31

    const float* Abase = A + (long)(bm + ar) * lda + ac4 * 4;
    const float* Bbase = BT ? (B + (long)(bn + ar) * ldb + ac4 * 4)
                            : (B + (long)bkr * ldb + bn + bc4 * 4);

    float4 a0, a1, b0, b1;

    auto fetch = [&](int kt) {
        {
            const float* p = Abase + kt * BK;
            a0 = *(const float4*)p;
            a1 = *(const float4*)(p + 64L * lda);
        }
        if (BT) {
            const float* p = Bbase + kt * BK;
            b0 = (bn + ar      < N) ? *(const float4*)p               : make_float4(0.f,0.f,0.f,0.f);
            b1 = (bn + ar + 64 < N) ? *(const float4*)(p + 64L * ldb) : make_float4(0.f,0.f,0.f,0.f);
        } else {
            const float* p = Bbase + (long)kt * BK * ldb;
            b0 = *(const float4*)p;
            b1 = *(const float4*)(p + 8L * ldb);
        }
    };

    auto put = [&](int buf) {
        As[buf][ac4*4+0][ar]    = a0.x;
        As[buf][ac4*4+1][ar]    = a0.y;
        As[buf][ac4*4+2][ar]    = a0.z;
        As[buf][ac4*4+3][ar]    = a0.w;
        As[buf][ac4*4+0][ar+64] = a1.x;
        As[buf][ac4*4+1][ar+64] = a1.y;
        As[buf][ac4*4+2][ar+64] = a1.z;
        As[buf][ac4*4+3][ar+64] = a1.w;
        if (BT) {
            Bs[buf][ac4*4+0][ar]    = b0.x;
            Bs[buf][ac4*4+1][ar]    = b0.y;
            Bs[buf][ac4*4+2][ar]    = b0.z;
            Bs[buf][ac4*4+3][ar]    = b0.w;
            Bs[buf][ac4*4+0][ar+64] = b1.x;
            Bs[buf][ac4*4+1][ar+64] = b1.y;
            Bs[buf][ac4*4+2][ar+64] = b1.z;
            Bs[buf][ac4*4+3][ar+64] = b1.w;
        } else {
            *(float4*)&Bs[buf][bkr    ][bc4*4] = b0;
            *(float4*)&Bs[buf][bkr + 8][bc4*4] = b1;
        }
    };

    float acc[TM][TN];
    #pragma unroll
    for (int i = 0; i < TM; i++)
        #pragma unroll
        for (int j = 0; j < TN; j++) acc[i][j] = 0.f;

    const int nkt = K / BK;
    fetch(0);
    put(0);
    __syncthreads();

    int buf = 0;
    for (int kt = 0; kt < nkt; kt++) {
        const bool more = (kt + 1 < nkt);
        if (more) fetch(kt + 1);

        #pragma unroll
        for (int k = 0; k < BK; k++) {
            float af[TM], bf[TN];
            #pragma unroll
            for (int i = 0; i < TM; i++) af[i] = As[buf][k][ty * TM + i];
            #pragma unroll
            for (int j = 0; j < TN; j++) bf[j] = Bs[buf][k][tx * TN + j];
            #pragma unroll
            for (int i = 0; i < TM; i++)
                #pragma unroll
                for (int j = 0; j < TN; j++)
                    acc[i][j] = fmaf(af[i], bf[j], acc[i][j]);
        }

        if (more) {
            put(buf ^ 1);
            __syncthreads();
            buf ^= 1;
        }
    }

    // Epilogue
    #pragma unroll
    for (int i = 0; i < TM; i++) {
        const long row = bm + ty * TM + i;
        float* Crow = C + row * (long)ldc;
        const float* injrow = INJ ? (inj + row * (long)S_DIM) : nullptr;
        #pragma unroll
        for (int j = 0; j < TN; j++) {
            const int col = bn + tx * TN + j;
            if (col < N) {
                float v = acc[i][j];
                if (INJ)  { if (col < S_DIM) v += injrow[col]; }
                if (BIAS) v += bias[col];
                if (RELU) v = fmaxf(v, 0.f);
                Crow[col] = v;
            }
        }
    }
}

// Z1[:, :S_DIM] = relu(E)   (rest of Z1 is implicitly zero; t=1 GEMM uses K=S_DIM)
__global__ void relu_scatter(const float* __restrict__ E, float* __restrict__ Z)
{
    int i = blockIdx.x * blockDim.x + threadIdx.x;
    if (i < BATCH * S_DIM) {
        int b = i >> 10;          // / S_DIM
        int s = i & (S_DIM - 1);  // % S_DIM
        Z[(long)b * TOTAL + s] = fmaxf(E[i], 0.f);
    }
}

extern "C" void kernel_launch(void* const* d_in, const int* in_sizes, int n_in,
                              void* d_out, int out_size)
{
    const float* x  = (const float*)d_in[0];
    const float* W  = (const float*)d_in[1];
    const float* Wp = (const float*)d_in[2];
    const float* bp = (const float*)d_in[3];
    const float* Wo = (const float*)d_in[4];
    const float* bo = (const float*)d_in[5];
    float* out = (float*)d_out;

    float *E, *Za, *Zb;
    cudaGetSymbolAddress((void**)&E,  g_E);
    cudaGetSymbolAddress((void**)&Za, g_Za);
    cudaGetSymbolAddress((void**)&Zb, g_Zb);

    const dim3 blk(256);
    const dim3 gridFull(TOTAL / BN, BATCH / BM);   // 32 x 16
    const dim3 gridProj(S_DIM / BN, BATCH / BM);   // 8 x 16
    const dim3 gridOut((NC + BN - 1) / BN, BATCH / BM);

    // E = x @ Wp^T + bp
    gemm_k<true, false, false, true><<<gridProj, blk>>>(
        x, IN_DIM, Wp, IN_DIM, E, S_DIM, S_DIM, IN_DIM, nullptr, bp);

    // t=0: Z1 = relu([E, 0])
    relu_scatter<<<(BATCH * S_DIM + 255) / 256, blk>>>(E, Za);

    // t=1: Z2 = relu(Z1 @ W), effective K = S_DIM (only first 1024 cols of Z1 nonzero)
    gemm_k<false, true, false, false><<<gridFull, blk>>>(
        Za, TOTAL, W, TOTAL, Zb, TOTAL, TOTAL, S_DIM, nullptr, nullptr);

    // t=2..9: full steps, ping-pong Zb<->Za; injection of E at t=5
    for (int t = 2; t <= 9; t++) {
        const float* Ain = (t % 2 == 0) ? Zb : Za;
        float*       Cot = (t % 2 == 0) ? Za : Zb;
        if (t == 5)
            gemm_k<false, true, true, false><<<gridFull, blk>>>(
                Ain, TOTAL, W, TOTAL, Cot, TOTAL, TOTAL, TOTAL, E, nullptr);
        else
            gemm_k<false, true, false, false><<<gridFull, blk>>>(
                Ain, TOTAL, W, TOTAL, Cot, TOTAL, TOTAL, TOTAL, nullptr, nullptr);
    }
    // Z10 ends in Zb

    // out = Z10[:, S+I:] @ Wo^T + bo
    gemm_k<true, false, false, true><<<gridOut, blk>>>(
        Zb + (S_DIM + I_DIM), TOTAL, Wo, O_DIMX, out, NC, NC, O_DIMX, nullptr, bo);
}

// round 3
// speedup vs baseline: 2.4003x; 2.4003x over previous
#include <cuda_runtime.h>
#include <cuda_bf16.h>
#include <cstdint>

// ---------------- problem constants ----------------
#define S_DIMX 1024
#define TOT    4096
#define BATCHX 2048
#define INDIM  1024
#define NCLS   1000

// ---------------- scratch (no cudaMalloc allowed) ----------------
__device__ __nv_bfloat16 g_WTh[(size_t)TOT * TOT];   // W^T hi (K-major [N,K])
__device__ __nv_bfloat16 g_WTl[(size_t)TOT * TOT];   // W^T lo
__device__ __nv_bfloat16 g_Wph[S_DIMX * INDIM];
__device__ __nv_bfloat16 g_Wpl[S_DIMX * INDIM];
__device__ __nv_bfloat16 g_Woh[NCLS * 1024];
__device__ __nv_bfloat16 g_Wol[NCLS * 1024];
__device__ __nv_bfloat16 g_xh[BATCHX * INDIM];
__device__ __nv_bfloat16 g_xl[BATCHX * INDIM];
__device__ float         g_E[BATCHX * S_DIMX];
__device__ __nv_bfloat16 g_Z1h[BATCHX * S_DIMX];     // compact relu(E) split (K=1024 trick)
__device__ __nv_bfloat16 g_Z1l[BATCHX * S_DIMX];
__device__ __nv_bfloat16 g_Zah[(size_t)BATCHX * TOT];
__device__ __nv_bfloat16 g_Zal[(size_t)BATCHX * TOT];
__device__ __nv_bfloat16 g_Zbh[(size_t)BATCHX * TOT];
__device__ __nv_bfloat16 g_Zbl[(size_t)BATCHX * TOT];

// ---------------- PTX helpers (sm_100 baseline-legal only) ----------------
__device__ __forceinline__ uint32_t smem_u32(const void* p) {
    uint32_t a;
    asm("{ .reg .u64 t; cvta.to.shared.u64 t, %1; cvt.u32.u64 %0, t; }" : "=r"(a) : "l"(p));
    return a;
}
__device__ __forceinline__ void cp16(uint32_t dst, const void* src, bool pred) {
    asm volatile("cp.async.cg.shared.global [%0], [%1], 16, %2;"
                 :: "r"(dst), "l"(src), "r"(pred ? 16u : 0u) : "memory");
}
__device__ __forceinline__ void cp_commit() {
    asm volatile("cp.async.commit_group;" ::: "memory");
}
template<int N>
__device__ __forceinline__ void cp_wait() {
    asm volatile("cp.async.wait_group %0;" :: "n"(N) : "memory");
}
__device__ __forceinline__ void ldsm4(uint32_t* r, uint32_t addr) {
    asm volatile("ldmatrix.sync.aligned.m8n8.x4.shared.b16 {%0,%1,%2,%3}, [%4];"
                 : "=r"(r[0]), "=r"(r[1]), "=r"(r[2]), "=r"(r[3]) : "r"(addr));
}
__device__ __forceinline__ void mma16816(float* c, const uint32_t* a, uint32_t b0, uint32_t b1) {
    asm volatile("mma.sync.aligned.m16n8k16.row.col.f32.bf16.bf16.f32 "
                 "{%0,%1,%2,%3},{%4,%5,%6,%7},{%8,%9},{%0,%1,%2,%3};"
                 : "+f"(c[0]), "+f"(c[1]), "+f"(c[2]), "+f"(c[3])
                 : "r"(a[0]), "r"(a[1]), "r"(a[2]), "r"(a[3]), "r"(b0), "r"(b1));
}
__device__ __forceinline__ void split_f32(float v, __nv_bfloat16& h, __nv_bfloat16& l) {
    h = __float2bfloat16_rn(v);
    l = __float2bfloat16_rn(v - __bfloat162float(h));
}

// ---------------- GEMM config ----------------
#define BM 128
#define BN 128
#define KC 32
#define ROWB 80                     // padded row bytes (32 bf16 = 64B data + 16B pad)
#define TILE_BYTES (128 * ROWB)     // 10240
#define AH_OFF 0
#define AL_OFF (1 * TILE_BYTES)
#define BH_OFF (2 * TILE_BYTES)
#define BL_OFF (3 * TILE_BYTES)
#define STAGE (4 * TILE_BYTES)      // 40960
#define SMEM_TOTAL (2 * STAGE)      // 81920

// D[M,N] = A[M,K] @ B[N,K]^T  via 3-term bf16 split on mma.sync (HMMA).
// MODE 0: Cf32 = v (+bias), guarded by col < Nvalid
// MODE 1: Ch/Cl = split(relu(v)) ; optional INJ adds Einj (block col < S_DIMX)
// MODE 2: Cf32 = v (+bias) [E], and Ch/Cl = split(relu(v))  [proj fused]
template<int MODE, bool INJ, bool BIAS>
__global__ __launch_bounds__(256)
void gemm_tc(const __nv_bfloat16* __restrict__ Ah, const __nv_bfloat16* __restrict__ Al, int lda,
             const __nv_bfloat16* __restrict__ Bh, const __nv_bfloat16* __restrict__ Bl, int ldb,
             int Nvalid, int K,
             float* __restrict__ Cf, int ldc,
             __nv_bfloat16* __restrict__ Ch, __nv_bfloat16* __restrict__ Cl, int ldz,
             const float* __restrict__ bias, const float* __restrict__ Einj)
{
    extern __shared__ char smem[];
    const uint32_t sbase = smem_u32(smem);
    const int tid = threadIdx.x;
    const int wid = tid >> 5, lid = tid & 31;
    const int wm = wid & 3;         // M warp 0..3 (32 rows each)
    const int wn = wid >> 2;        // N warp 0..1 (64 cols each)
    const int bm = blockIdx.y * BM;
    const int bn = blockIdx.x * BN;

    // ---- global->shared mapping: seg = 16B segment, r0 = row
    const int seg = tid & 3;
    const int r0  = tid >> 2;       // 0..63 (rows r0, r0+64)

    const __nv_bfloat16* Abh = Ah + (long)bm * lda;
    const __nv_bfloat16* Abl = Al + (long)bm * lda;
    const __nv_bfloat16* Bbh = Bh + (long)bn * ldb;
    const __nv_bfloat16* Bbl = Bl + (long)bn * ldb;
    const int validB = Nvalid - bn;

    auto load_stage = [&](int c, int stg) {
        const uint32_t st = sbase + stg * STAGE;
        const long koff = (long)c * KC + seg * 8;
        #pragma unroll
        for (int i = 0; i < 128; i += 64) {
            const int row = r0 + i;
            const uint32_t doff = row * ROWB + seg * 16;
            cp16(st + AH_OFF + doff, Abh + (long)row * lda + koff, true);
            cp16(st + AL_OFF + doff, Abl + (long)row * lda + koff, true);
            const bool ok = row < validB;
            cp16(st + BH_OFF + doff, Bbh + (long)row * ldb + koff, ok);
            cp16(st + BL_OFF + doff, Bbl + (long)row * ldb + koff, ok);
        }
        cp_commit();
    };

    float acc[2][8][4];
    #pragma unroll
    for (int mt = 0; mt < 2; mt++)
        #pragma unroll
        for (int nt = 0; nt < 8; nt++)
            #pragma unroll
            for (int q = 0; q < 4; q++) acc[mt][nt][q] = 0.f;

    const int nk = K / KC;
    load_stage(0, 0);

    for (int c = 0; c < nk; c++) {
        if (c + 1 < nk) {
            load_stage(c + 1, (c + 1) & 1);
            cp_wait<1>();
        } else {
            cp_wait<0>();
        }
        __syncthreads();

        const uint32_t st = sbase + (c & 1) * STAGE;
        #pragma unroll
        for (int k16 = 0; k16 < 2; k16++) {
            const int colByte = k16 * 32 + ((lid >> 4) & 1) * 16;
            uint32_t aH[2][4], aL[2][4], bH[4][4], bL[4][4];
            #pragma unroll
            for (int mt = 0; mt < 2; mt++) {
                const int row = wm * 32 + mt * 16 + ((lid >> 3) & 1) * 8 + (lid & 7);
                const uint32_t off = row * ROWB + colByte;
                ldsm4(aH[mt], st + AH_OFF + off);
                ldsm4(aL[mt], st + AL_OFF + off);
            }
            #pragma unroll
            for (int p = 0; p < 4; p++) {
                const int row = wn * 64 + p * 16 + ((lid >> 3) & 1) * 8 + (lid & 7);
                const uint32_t off = row * ROWB + colByte;
                ldsm4(bH[p], st + BH_OFF + off);
                ldsm4(bL[p], st + BL_OFF + off);
            }
            #pragma unroll
            for (int mt = 0; mt < 2; mt++)
                #pragma unroll
                for (int nt = 0; nt < 8; nt++) {
                    const int p = nt >> 1, o = nt & 1;
                    mma16816(acc[mt][nt], aH[mt], bH[p][o], bH[p][o + 2]);
                    mma16816(acc[mt][nt], aH[mt], bL[p][o], bL[p][o + 2]);
                    mma16816(acc[mt][nt], aL[mt], bH[p][o], bH[p][o + 2]);
                }
        }
        __syncthreads();
    }

    // ---- epilogue (registers -> global, fused)
    const bool doInj = INJ && (bn < S_DIMX);
    #pragma unroll
    for (int mt = 0; mt < 2; mt++) {
        #pragma unroll
        for (int half = 0; half < 2; half++) {
            const int r = bm + wm * 32 + mt * 16 + half * 8 + (lid >> 2);
            #pragma unroll
            for (int nt = 0; nt < 8; nt++) {
                const int col = bn + wn * 64 + nt * 8 + (lid & 3) * 2;
                float v0 = acc[mt][nt][half * 2 + 0];
                float v1 = acc[mt][nt][half * 2 + 1];
                if (doInj) {
                    const float* ep = Einj + (long)r * S_DIMX + col;
                    v0 += ep[0]; v1 += ep[1];
                }
                if (BIAS) {
                    if (MODE != 0 || col < Nvalid)     v0 += bias[col];
                    if (MODE != 0 || col + 1 < Nvalid) v1 += bias[col + 1];
                }
                if (MODE == 0) {
                    float* cp = Cf + (long)r * ldc + col;
                    if (col < Nvalid)     cp[0] = v0;
                    if (col + 1 < Nvalid) cp[1] = v1;
                } else {
                    if (MODE == 2) {
                        // pre-relu fp32 (E)
                        *(float2*)(Cf + (long)r * ldc + col) = make_float2(v0, v1);
                    }
                    v0 = fmaxf(v0, 0.f);
                    v1 = fmaxf(v1, 0.f);
                    __nv_bfloat16 h0, l0, h1, l1;
                    split_f32(v0, h0, l0);
                    split_f32(v1, h1, l1);
                    __nv_bfloat162 hh; hh.x = h0; hh.y = h1;
                    __nv_bfloat162 ll; ll.x = l0; ll.y = l1;
                    *(__nv_bfloat162*)(Ch + (long)r * ldz + col) = hh;
                    *(__nv_bfloat162*)(Cl + (long)r * ldz + col) = ll;
                }
            }
        }
    }
}

// ---------------- split / transpose kernels ----------------
__global__ void k_split_transpose(const float* __restrict__ W,
                                  __nv_bfloat16* __restrict__ Th,
                                  __nv_bfloat16* __restrict__ Tl)
{
    __shared__ float t[32][33];
    const int n0 = blockIdx.x * 32, k0 = blockIdx.y * 32;
    const int tx = threadIdx.x, ty = threadIdx.y;  // 32 x 8
    #pragma unroll
    for (int i = 0; i < 32; i += 8)
        t[ty + i][tx] = W[(long)(k0 + ty + i) * TOT + n0 + tx];
    __syncthreads();
    #pragma unroll
    for (int i = 0; i < 32; i += 8) {
        float v = t[tx][ty + i];                 // = W[k0+tx][n0+ty+i]
        __nv_bfloat16 h, l;
        split_f32(v, h, l);
        const long o = (long)(n0 + ty + i) * TOT + k0 + tx;
        Th[o] = h; Tl[o] = l;
    }
}

__global__ void k_split(const float* __restrict__ src,
                        __nv_bfloat16* __restrict__ h,
                        __nv_bfloat16* __restrict__ l, int n)
{
    int i = blockIdx.x * 256 + threadIdx.x;
    if (i < n) {
        __nv_bfloat16 a, b;
        split_f32(src[i], a, b);
        h[i] = a; l[i] = b;
    }
}

// ---------------- launch ----------------
extern "C" void kernel_launch(void* const* d_in, const int* in_sizes, int n_in,
                              void* d_out, int out_size)
{
    const float* x  = (const float*)d_in[0];
    const float* W  = (const float*)d_in[1];
    const float* Wp = (const float*)d_in[2];
    const float* bp = (const float*)d_in[3];
    const float* Wo = (const float*)d_in[4];
    const float* bo = (const float*)d_in[5];
    float* out = (float*)d_out;

    __nv_bfloat16 *WTh, *WTl, *Wph, *Wpl, *Woh, *Wol, *xh, *xl;
    __nv_bfloat16 *Z1h, *Z1l, *Zah, *Zal, *Zbh, *Zbl;
    float* E;
    cudaGetSymbolAddress((void**)&WTh, g_WTh);
    cudaGetSymbolAddress((void**)&WTl, g_WTl);
    cudaGetSymbolAddress((void**)&Wph, g_Wph);
    cudaGetSymbolAddress((void**)&Wpl, g_Wpl);
    cudaGetSymbolAddress((void**)&Woh, g_Woh);
    cudaGetSymbolAddress((void**)&Wol, g_Wol);
    cudaGetSymbolAddress((void**)&xh,  g_xh);
    cudaGetSymbolAddress((void**)&xl,  g_xl);
    cudaGetSymbolAddress((void**)&E,   g_E);
    cudaGetSymbolAddress((void**)&Z1h, g_Z1h);
    cudaGetSymbolAddress((void**)&Z1l, g_Z1l);
    cudaGetSymbolAddress((void**)&Zah, g_Zah);
    cudaGetSymbolAddress((void**)&Zal, g_Zal);
    cudaGetSymbolAddress((void**)&Zbh, g_Zbh);
    cudaGetSymbolAddress((void**)&Zbl, g_Zbl);

    cudaFuncSetAttribute(gemm_tc<2, false, true>,
                         cudaFuncAttributeMaxDynamicSharedMemorySize, SMEM_TOTAL);
    cudaFuncSetAttribute(gemm_tc<1, false, false>,
                         cudaFuncAttributeMaxDynamicSharedMemorySize, SMEM_TOTAL);
    cudaFuncSetAttribute(gemm_tc<1, true, false>,
                         cudaFuncAttributeMaxDynamicSharedMemorySize, SMEM_TOTAL);
    cudaFuncSetAttribute(gemm_tc<0, false, true>,
                         cudaFuncAttributeMaxDynamicSharedMemorySize, SMEM_TOTAL);

    // ---- splits (one-time per launch)
    k_split_transpose<<<dim3(TOT / 32, TOT / 32), dim3(32, 8)>>>(W, WTh, WTl);
    k_split<<<(S_DIMX * INDIM + 255) / 256, 256>>>(Wp, Wph, Wpl, S_DIMX * INDIM);
    k_split<<<(NCLS * 1024 + 255) / 256, 256>>>(Wo, Woh, Wol, NCLS * 1024);
    k_split<<<(BATCHX * INDIM + 255) / 256, 256>>>(x, xh, xl, BATCHX * INDIM);

    const dim3 blk(256);
    const dim3 gProj(S_DIMX / BN, BATCHX / BM);           // 8 x 16
    const dim3 gStep(TOT / BN, BATCHX / BM);              // 32 x 16
    const dim3 gOut((NCLS + BN - 1) / BN, BATCHX / BM);   // 8 x 16

    // proj: E = x @ Wp^T + bp ; Z1 = split(relu(E))   [t=0 fused]
    gemm_tc<2, false, true><<<gProj, blk, SMEM_TOTAL>>>(
        xh, xl, INDIM, Wph, Wpl, INDIM, S_DIMX, INDIM,
        E, S_DIMX, Z1h, Z1l, S_DIMX, bp, nullptr);

    // t=1: Za = split(relu(Z1 @ W)), K = 1024 (Z1 nonzero only in first S_DIM cols)
    gemm_tc<1, false, false><<<gStep, blk, SMEM_TOTAL>>>(
        Z1h, Z1l, S_DIMX, WTh, WTl, TOT, TOT, S_DIMX,
        nullptr, 0, Zah, Zal, TOT, nullptr, nullptr);

    // t=2..9: full steps; inject E at t=5
    for (int t = 2; t <= 9; t++) {
        const __nv_bfloat16* Aih = (t % 2 == 0) ? Zah : Zbh;
        const __nv_bfloat16* Ail = (t % 2 == 0) ? Zal : Zbl;
        __nv_bfloat16* Coh = (t % 2 == 0) ? Zbh : Zah;
        __nv_bfloat16* Col = (t % 2 == 0) ? Zbl : Zal;
        if (t == 5)
            gemm_tc<1, true, false><<<gStep, blk, SMEM_TOTAL>>>(
                Aih, Ail, TOT, WTh, WTl, TOT, TOT, TOT,
                nullptr, 0, Coh, Col, TOT, nullptr, E);
        else
            gemm_tc<1, false, false><<<gStep, blk, SMEM_TOTAL>>>(
                Aih, Ail, TOT, WTh, WTl, TOT, TOT, TOT,
                nullptr, 0, Coh, Col, TOT, nullptr, nullptr);
    }
    // final state: t=9 writes Za

    // readout: out = Z10[:, 3072:] @ Wo^T + bo
    gemm_tc<0, false, true><<<gOut, blk, SMEM_TOTAL>>>(
        Zah + (S_DIMX + 2048), Zal + (S_DIMX + 2048), TOT, Woh, Wol, 1024, NCLS, 1024,
        out, NCLS, nullptr, nullptr, 0, bo, nullptr);
}